// round 16
// baseline (speedup 1.0000x reference)
#include <cuda_runtime.h>
#include <cuda_bf16.h>
#include <cstdint>

#define NB 8
#define CD 256
#define LD 6400
#define NHEADS 8
#define HC 32

// Scratch (device globals -- no allocation allowed)
__device__ float g_Q[NB * CD * LD];
__device__ float g_K[NB * CD * LD];   // holds bf16 K (GEMM writes bf16 here)
__device__ float g_V[NB * CD * LD];   // holds bf16 V
__device__ float g_CTX[NB * NHEADS * HC * HC];
__device__ float g_ksum[NB * CD];
__device__ __nv_bfloat16 g_Qbf[NB * CD * LD];
__device__ __nv_bfloat16 g_Kbf[NB * CD * LD];
__device__ __nv_bfloat16 g_Vbf[NB * CD * LD];
__device__ __nv_bfloat16 g_ATTbf[NB * CD * LD];
__device__ __nv_bfloat16 g_Wt[4 * 256 * 256];   // k-major bf16: Wq,Wk,Wv,Wr

// ---------------------------------------------------------------------------
// mma.sync / ldmatrix / cp.async helpers (baseline PTX, works on compute_103)
// ---------------------------------------------------------------------------
__device__ __forceinline__ uint32_t smem_u32(const void* p) {
    uint32_t a;
    asm("{ .reg .u64 t; cvta.to.shared.u64 t, %1; cvt.u32.u64 %0, t; }"
        : "=r"(a) : "l"(p));
    return a;
}

__device__ __forceinline__ void ldsm4t(uint32_t* r, uint32_t addr) {
    asm volatile("ldmatrix.sync.aligned.m8n8.x4.trans.shared.b16 {%0,%1,%2,%3}, [%4];"
                 : "=r"(r[0]), "=r"(r[1]), "=r"(r[2]), "=r"(r[3]) : "r"(addr));
}

__device__ __forceinline__ void mma16816(float* c, uint32_t a0, uint32_t a1,
                                         uint32_t a2, uint32_t a3,
                                         uint32_t b0, uint32_t b1) {
    asm volatile(
        "mma.sync.aligned.m16n8k16.row.col.f32.bf16.bf16.f32 "
        "{%0,%1,%2,%3}, {%4,%5,%6,%7}, {%8,%9}, {%0,%1,%2,%3};"
        : "+f"(c[0]), "+f"(c[1]), "+f"(c[2]), "+f"(c[3])
        : "r"(a0), "r"(a1), "r"(a2), "r"(a3), "r"(b0), "r"(b1));
}

__device__ __forceinline__ void cpasync16(uint32_t saddr, const void* g) {
    asm volatile("cp.async.cg.shared.global [%0], [%1], 16;"
                 :: "r"(saddr), "l"(g) : "memory");
}
__device__ __forceinline__ void cpasync_commit() {
    asm volatile("cp.async.commit_group;" ::: "memory");
}
__device__ __forceinline__ void cpasync_wait0() {
    asm volatile("cp.async.wait_group 0;" ::: "memory");
}
__device__ __forceinline__ void cpasync_wait1() {
    asm volatile("cp.async.wait_group 1;" ::: "memory");
}

// ---------------------------------------------------------------------------
// Fused conversion: q/k/v fp32 -> bf16 (MLP=4) + W transposes + CTX/ksum zero.
// y==3: blocks [0,64) transpose W; blocks [64,328) zero CTX (65536) + ksum (2048).
// ---------------------------------------------------------------------------
#define CVT_STRIDE 819200   // (NB*CD*LD/4) / 4 float4s per j-slice
#define CTX_ELEMS (NB * NHEADS * HC * HC)   // 65536

__global__ __launch_bounds__(256) void cvt_all_kernel(
    const float* __restrict__ qf, const float* __restrict__ kf,
    const float* __restrict__ vf,
    const float* __restrict__ Wq, const float* __restrict__ Wk,
    const float* __restrict__ Wv, const float* __restrict__ Wr)
{
    const int y = blockIdx.y;
    if (y < 3) {
        const float* src = (y == 0) ? kf : (y == 1) ? qf : vf;
        __nv_bfloat16* dst = (y == 0) ? g_Kbf : (y == 1) ? g_Qbf : g_Vbf;
        const float4* s4 = (const float4*)src;
        const size_t base = (size_t)blockIdx.x * 256 + threadIdx.x;
        float4 v[4];
#pragma unroll
        for (int j = 0; j < 4; ++j) v[j] = s4[base + (size_t)j * CVT_STRIDE];
#pragma unroll
        for (int j = 0; j < 4; ++j) {
            union { __nv_bfloat162 h[2]; unsigned long long u; } u;
            u.h[0] = __float22bfloat162_rn(make_float2(v[j].x, v[j].y));
            u.h[1] = __float22bfloat162_rn(make_float2(v[j].z, v[j].w));
            *(unsigned long long*)&dst[(base + (size_t)j * CVT_STRIDE) * 4] = u.u;
        }
    } else {
        if (blockIdx.x < 64) {
            int t = blockIdx.x * 256 + threadIdx.x;   // 0..16383
            const float* Ws[4] = {Wq, Wk, Wv, Wr};
#pragma unroll
            for (int w = 0; w < 4; ++w) {
                const float* W = Ws[w];
                __nv_bfloat16* D = g_Wt + w * 65536;
                for (int idx = t; idx < 65536; idx += 16384) {
                    int m = idx >> 8, k = idx & 255;
                    D[k * 256 + m] = __float2bfloat16(W[idx]);   // W[m*256+k]
                }
            }
        } else if (blockIdx.x < 328) {
            int t = (blockIdx.x - 64) * 256 + threadIdx.x;   // 0..67583
            if (t < CTX_ELEMS) g_CTX[t] = 0.0f;
            int j = t - CTX_ELEMS;
            if (j >= 0 && j < NB * CD) g_ksum[j] = 0.0f;
        }
    }
}

// ---------------------------------------------------------------------------
// HMMA GEMM: Y[n, m, l] = sum_k Wt[k,m] * Xbf[n,k,l] + bias[m] (+ resid)
// Output stored fp32 or bf16 depending on (bfmask >> proj) & 1.
// Block tile 128(m) x 128(l), BK=32, 8 warps, 3-stage cp.async pipeline.
// ---------------------------------------------------------------------------
#define SB 136                     // bf16 row stride (272B, conflict-free ldsm)
#define REG_EL (32 * SB)           // 4352 bf16 per operand region
#define STAGE_BYTES (2 * REG_EL * 2)   // A + B regions = 17408 bytes
#define GEMM_SMEM (3 * STAGE_BYTES)    // 52224 bytes

__global__ __launch_bounds__(256, 2) void hmma_gemm_kernel(
    const __nv_bfloat16* __restrict__ X0, const __nv_bfloat16* __restrict__ X1,
    const __nv_bfloat16* __restrict__ X2,
    const __nv_bfloat16* __restrict__ Wt0, const __nv_bfloat16* __restrict__ Wt1,
    const __nv_bfloat16* __restrict__ Wt2,
    const float* __restrict__ b0p, const float* __restrict__ b1p,
    const float* __restrict__ b2p,
    void* __restrict__ Y0v, void* __restrict__ Y1v, void* __restrict__ Y2v,
    const float* __restrict__ resid, int bfmask)
{
    extern __shared__ __align__(16) __nv_bfloat16 dsm[];

    const int tid  = threadIdx.x;
    const int wid  = tid >> 5;
    const int lane = tid & 31;
    const int l0   = blockIdx.x * 128;
    const int m0   = blockIdx.y * 128;
    const int proj = blockIdx.z >> 3;
    const int nb   = blockIdx.z & 7;

    const __nv_bfloat16* X;
    const __nv_bfloat16* Wt;
    const float* bias;
    void* Yv;
    if (proj == 0)      { X = X0; Wt = Wt0; bias = b0p; Yv = Y0v; }
    else if (proj == 1) { X = X1; Wt = Wt1; bias = b1p; Yv = Y1v; }
    else                { X = X2; Wt = Wt2; bias = b2p; Yv = Y2v; }
    const bool bf16out = (bfmask >> proj) & 1;

    const int m0w = (wid & 3) * 32;   // warp m offset in block
    const int n0w = (wid >> 2) * 64;  // warp n offset in block

    const __nv_bfloat16* Xn = X + (size_t)nb * CD * LD;
    const float* Rn = resid ? resid + (size_t)nb * CD * LD : nullptr;
    const size_t ybase = (size_t)nb * CD * LD;

    float acc[2][8][4];
#pragma unroll
    for (int i = 0; i < 2; i++)
#pragma unroll
        for (int j = 0; j < 8; j++)
#pragma unroll
            for (int e = 0; e < 4; e++) acc[i][j][e] = 0.0f;

    const uint32_t smBase = smem_u32(dsm);
    const uint32_t chunk = (uint32_t)((tid >> 4) * (SB * 2) + (tid & 15) * 16);
    const uint32_t aOff = (uint32_t)((lane & 15) * (SB * 2) +
                                     (m0w + ((lane >> 4) << 3)) * 2);
    const uint32_t bOff = (uint32_t)((lane & 15) * (SB * 2) +
                                     (n0w + ((lane >> 4) << 3)) * 2);
    const int g_k  = tid >> 4;    // 0..15
    const int g_c8 = (tid & 15) * 8;

#define ISSUE(c)                                                               \
    {                                                                          \
        uint32_t sb = smBase + ((c) % 3) * STAGE_BYTES;                        \
        const __nv_bfloat16* gA = Wt + ((c) * 32 + g_k) * 256 + m0 + g_c8;     \
        cpasync16(sb + chunk, gA);                                             \
        cpasync16(sb + chunk + 16 * SB * 2, gA + 16 * 256);                    \
        const __nv_bfloat16* gB =                                              \
            Xn + (size_t)((c) * 32 + g_k) * LD + l0 + g_c8;                    \
        cpasync16(sb + 2 * REG_EL + chunk, gB);                                \
        cpasync16(sb + 2 * REG_EL + chunk + 16 * SB * 2, gB + (size_t)16 * LD);\
        cpasync_commit();                                                      \
    }

    ISSUE(0);
    ISSUE(1);

#pragma unroll
    for (int c = 0; c < 8; ++c) {
        if (c < 7) cpasync_wait1(); else cpasync_wait0();
        __syncthreads();
        if (c < 6) ISSUE(c + 2);

        uint32_t aA = smBase + (c % 3) * STAGE_BYTES + aOff;
        uint32_t bA = aA - aOff + 2 * REG_EL + bOff;
#pragma unroll
        for (int ks = 0; ks < 2; ++ks) {
            uint32_t a4[2][4];
#pragma unroll
            for (int im = 0; im < 2; ++im)
                ldsm4t(a4[im], aA + (uint32_t)(ks * 16 * SB * 2 + im * 32));
#pragma unroll
            for (int jp = 0; jp < 4; ++jp) {
                uint32_t b4[4];
                ldsm4t(b4, bA + (uint32_t)(ks * 16 * SB * 2 + jp * 32));
#pragma unroll
                for (int im = 0; im < 2; ++im) {
                    // A fragment from transposed ldsm: {r0, r2, r1, r3}
                    mma16816(acc[im][jp * 2 + 0], a4[im][0], a4[im][2],
                             a4[im][1], a4[im][3], b4[0], b4[1]);
                    mma16816(acc[im][jp * 2 + 1], a4[im][0], a4[im][2],
                             a4[im][1], a4[im][3], b4[2], b4[3]);
                }
            }
        }
    }

    // ---- epilogue: regs -> global, + bias (+ residual); fp32 or bf16 store
    const int qr = lane >> 2;        // 0..7
    const int qc = (lane & 3) * 2;   // 0,2,4,6
#pragma unroll
    for (int im = 0; im < 2; ++im) {
        int mA = m0 + m0w + im * 16 + qr;
        int mB = mA + 8;
        float bA = bias[mA];
        float bB = bias[mB];
#pragma unroll
        for (int jn = 0; jn < 8; ++jn) {
            int n = l0 + n0w + jn * 8 + qc;
            size_t gA = ybase + (size_t)mA * LD + n;
            size_t gB = ybase + (size_t)mB * LD + n;
            float o0 = acc[im][jn][0] + bA;
            float o1 = acc[im][jn][1] + bA;
            float o2 = acc[im][jn][2] + bB;
            float o3 = acc[im][jn][3] + bB;
            if (Rn) {
                float2 rA = *(const float2*)(Rn + (size_t)mA * LD + n);
                float2 rB = *(const float2*)(Rn + (size_t)mB * LD + n);
                o0 += rA.x; o1 += rA.y; o2 += rB.x; o3 += rB.y;
            }
            if (bf16out) {
                __nv_bfloat16* Yb = (__nv_bfloat16*)Yv;
                *(__nv_bfloat162*)(Yb + gA) =
                    __float22bfloat162_rn(make_float2(o0, o1));
                *(__nv_bfloat162*)(Yb + gB) =
                    __float22bfloat162_rn(make_float2(o2, o3));
            } else {
                float* Yf = (float*)Yv;
                float2 vA = {o0, o1};
                float2 vB = {o2, o3};
                *(float2*)(Yf + gA) = vA;
                *(float2*)(Yf + gB) = vB;
            }
        }
    }
}

// ---------------------------------------------------------------------------
// context[n,h,kc,vc] = sum_l exp(K[n,h,kc,l]) * V[n,h,vc,l]   (unnormalized)
// K, V read as bf16. Register tile 4kc x 8vc (3x LDS.128 per 32 FMA).
// Staging: row-per-thread float4 STS (conflict-free, R14-verified).
// ---------------------------------------------------------------------------
#define CPAD 36   // floats per l-row (16B aligned, conflict-free fp4 reads)

__global__ __launch_bounds__(256) void context_kernel()
{
    __shared__ float skT[128][CPAD];
    __shared__ float svT[128][CPAD];
    const __nv_bfloat16* Kb = (const __nv_bfloat16*)g_K;
    const __nv_bfloat16* Vb = (const __nv_bfloat16*)g_V;
    const int n = blockIdx.z, h = blockIdx.y;
    const size_t base = (((size_t)n * NHEADS + h) * HC) * LD;
    const int rowbase = n * CD + h * HC;
    const int tid = threadIdx.x;
    const int lgrp = tid >> 5;        // 0..7 (16 l's each)
    const int t32  = tid & 31;
    const int kc0  = (t32 >> 2) * 4;  // 0,4,..,28
    const int vc0  = (t32 & 3) * 8;   // 0,8,16,24
    const bool do_ksum = ((t32 & 3) == 0);

    // staging assignment: one l-row, 16 channels per thread
    const int sl  = tid & 127;
    const int sc0 = (tid >> 7) * 16;

    float acc[4][8];
#pragma unroll
    for (int i = 0; i < 4; ++i)
#pragma unroll
        for (int j = 0; j < 8; ++j) acc[i][j] = 0.0f;
    float ks[4] = {0.f, 0.f, 0.f, 0.f};

    __nv_bfloat16 rk[16], rv[16];

#define CTX_LOAD(t)                                                            \
    {                                                                          \
        const int l0c = blockIdx.x * 640 + (t) * 128;                          \
        _Pragma("unroll")                                                      \
        for (int j = 0; j < 16; ++j) {                                         \
            rk[j] = Kb[base + (size_t)(sc0 + j) * LD + l0c + sl];              \
            rv[j] = Vb[base + (size_t)(sc0 + j) * LD + l0c + sl];              \
        }                                                                      \
    }

#define CTX_STORE()                                                            \
    {                                                                          \
        _Pragma("unroll")                                                      \
        for (int j4 = 0; j4 < 4; ++j4) {                                       \
            float4 a;                                                          \
            a.x = __expf(__bfloat162float(rk[j4 * 4 + 0]));                    \
            a.y = __expf(__bfloat162float(rk[j4 * 4 + 1]));                    \
            a.z = __expf(__bfloat162float(rk[j4 * 4 + 2]));                    \
            a.w = __expf(__bfloat162float(rk[j4 * 4 + 3]));                    \
            *(float4*)&skT[sl][sc0 + j4 * 4] = a;                              \
            float4 b;                                                          \
            b.x = __bfloat162float(rv[j4 * 4 + 0]);                            \
            b.y = __bfloat162float(rv[j4 * 4 + 1]);                            \
            b.z = __bfloat162float(rv[j4 * 4 + 2]);                            \
            b.w = __bfloat162float(rv[j4 * 4 + 3]);                            \
            *(float4*)&svT[sl][sc0 + j4 * 4] = b;                              \
        }                                                                      \
    }

    CTX_LOAD(0);

    for (int t = 0; t < 5; ++t) {
        CTX_STORE();
        __syncthreads();
        if (t < 4) CTX_LOAD(t + 1);   // LDGs in flight during compute

#pragma unroll 4
        for (int li = 0; li < 16; ++li) {
            int l = lgrp * 16 + li;
            float4 a4 = *(const float4*)&skT[l][kc0];
            float4 b4 = *(const float4*)&svT[l][vc0];
            float4 b5 = *(const float4*)&svT[l][vc0 + 4];
            float a[4] = {a4.x, a4.y, a4.z, a4.w};
            float b[8] = {b4.x, b4.y, b4.z, b4.w, b5.x, b5.y, b5.z, b5.w};
#pragma unroll
            for (int i = 0; i < 4; ++i)
#pragma unroll
                for (int j = 0; j < 8; ++j)
                    acc[i][j] += a[i] * b[j];
            if (do_ksum) {
                ks[0] += a[0]; ks[1] += a[1]; ks[2] += a[2]; ks[3] += a[3];
            }
        }
        __syncthreads();
    }

    if (do_ksum) {
#pragma unroll
        for (int i = 0; i < 4; ++i)
            atomicAdd(&g_ksum[rowbase + kc0 + i], ks[i]);
    }
    float* C = g_CTX + (((size_t)n * NHEADS + h) * HC) * HC;
#pragma unroll
    for (int i = 0; i < 4; ++i)
#pragma unroll
        for (int j = 0; j < 8; ++j)
            atomicAdd(&C[(kc0 + i) * HC + vc0 + j], acc[i][j]);
}

// ---------------------------------------------------------------------------
// attended[n,h,vc,l] = sum_kc (ctx[n,h,kc,vc]/ksum[kc]) * softmax_C(q)[n,h,kc,l]
// Writes bf16 directly for the recovery GEMM.
// ---------------------------------------------------------------------------
__global__ __launch_bounds__(128) void attend_kernel()
{
    __shared__ float4 sctx[32][8];
    const int n = blockIdx.z, h = blockIdx.y;
    const int tid = threadIdx.x;
    const int rowbase = n * CD + h * HC;
    {
        const float4* C = (const float4*)(g_CTX + (((size_t)n * NHEADS + h) * HC) * HC);
#pragma unroll
        for (int s = 0; s < 2; s++) {
            int idx = tid + s * 128;
            float inv = 1.0f / g_ksum[rowbase + (idx >> 3)];
            float4 v = C[idx];
            v.x *= inv; v.y *= inv; v.z *= inv; v.w *= inv;
            sctx[idx >> 3][idx & 7] = v;
        }
    }
    __syncthreads();

    const int l = blockIdx.x * 128 + tid;
    const size_t base = (((size_t)n * NHEADS + h) * HC) * LD + l;

    float q[HC];
    float mx = -1e30f;
#pragma unroll
    for (int c = 0; c < HC; c++) {
        q[c] = g_Q[base + (size_t)c * LD];
        mx = fmaxf(mx, q[c]);
    }
    float s = 0.0f;
#pragma unroll
    for (int c = 0; c < HC; c++) {
        q[c] = __expf(q[c] - mx);
        s += q[c];
    }
    float inv = 1.0f / s;
#pragma unroll
    for (int c = 0; c < HC; c++) q[c] *= inv;

    float acc[HC];
#pragma unroll
    for (int v = 0; v < HC; v++) acc[v] = 0.0f;

#pragma unroll
    for (int kc = 0; kc < HC; kc++) {
        float a = q[kc];
#pragma unroll
        for (int vq = 0; vq < 8; vq++) {
            float4 c4 = sctx[kc][vq];
            acc[vq * 4 + 0] += a * c4.x;
            acc[vq * 4 + 1] += a * c4.y;
            acc[vq * 4 + 2] += a * c4.z;
            acc[vq * 4 + 3] += a * c4.w;
        }
    }
#pragma unroll
    for (int v = 0; v < HC; v++)
        g_ATTbf[base + (size_t)v * LD] = __float2bfloat16(acc[v]);
}

// ---------------------------------------------------------------------------
extern "C" void kernel_launch(void* const* d_in, const int* in_sizes, int n_in,
                              void* d_out, int out_size)
{
    const float* qf = (const float*)d_in[0];
    const float* kf = (const float*)d_in[1];
    const float* vf = (const float*)d_in[2];
    const float* Wq = (const float*)d_in[3];
    const float* bq = (const float*)d_in[4];
    const float* Wk = (const float*)d_in[5];
    const float* bk = (const float*)d_in[6];
    const float* Wv = (const float*)d_in[7];
    const float* bv = (const float*)d_in[8];
    const float* Wr = (const float*)d_in[9];
    const float* br = (const float*)d_in[10];
    float* out = (float*)d_out;

    float *Q, *K, *V;
    __nv_bfloat16 *Qbf, *Kbf, *Vbf, *ATTbf, *Wt;
    cudaGetSymbolAddress((void**)&Q,     g_Q);
    cudaGetSymbolAddress((void**)&K,     g_K);
    cudaGetSymbolAddress((void**)&V,     g_V);
    cudaGetSymbolAddress((void**)&Qbf,   g_Qbf);
    cudaGetSymbolAddress((void**)&Kbf,   g_Kbf);
    cudaGetSymbolAddress((void**)&Vbf,   g_Vbf);
    cudaGetSymbolAddress((void**)&ATTbf, g_ATTbf);
    cudaGetSymbolAddress((void**)&Wt,    g_Wt);
    __nv_bfloat16* Wtq = Wt;
    __nv_bfloat16* Wtk = Wt + 65536;
    __nv_bfloat16* Wtv = Wt + 2 * 65536;
    __nv_bfloat16* Wtr = Wt + 3 * 65536;

    cudaFuncSetAttribute(hmma_gemm_kernel,
                         cudaFuncAttributeMaxDynamicSharedMemorySize, GEMM_SMEM);

    cvt_all_kernel<<<dim3(3200, 4), 256>>>(qf, kf, vf, Wq, Wk, Wv, Wr);    // 1

    // fused Q/K/V projections: proj = blockIdx.z >> 3
    // proj 0 = K (bf16 out), proj 1 = Q (fp32 out), proj 2 = V (bf16 out)
    dim3 fused_grid(LD / 128, CD / 128, 3 * NB);
    hmma_gemm_kernel<<<fused_grid, 256, GEMM_SMEM>>>(                      // 2
        Kbf, Qbf, Vbf, Wtk, Wtq, Wtv, bk, bq, bv, K, Q, V, nullptr, 0b101);

    context_kernel<<<dim3(10, NHEADS, NB), 256>>>();                       // 3
    attend_kernel<<<dim3(LD / 128, NHEADS, NB), 128>>>();                  // 4 (ncu)

    dim3 gemm_grid(LD / 128, CD / 128, NB);
    hmma_gemm_kernel<<<gemm_grid, 256, GEMM_SMEM>>>(                       // 5
        ATTbf, ATTbf, ATTbf, Wtr, Wtr, Wtr, br, br, br, out, out, out, qf, 0);
}

// round 17
// speedup vs baseline: 1.2165x; 1.2165x over previous
#include <cuda_runtime.h>
#include <cuda_bf16.h>
#include <cstdint>

#define NB 8
#define CD 256
#define LD 6400
#define NHEADS 8
#define HC 32

// Scratch (device globals -- no allocation allowed)
__device__ float g_Q[NB * CD * LD];
__device__ float g_K[NB * CD * LD];
__device__ float g_V[NB * CD * LD];
__device__ float g_CTX[NB * NHEADS * HC * HC];
__device__ float g_ksum[NB * CD];
__device__ __nv_bfloat16 g_ATTbf[NB * CD * LD];
__device__ __nv_bfloat16 g_Wt[4 * 256 * 256];   // k-major bf16: Wq,Wk,Wv,Wr

// ---------------------------------------------------------------------------
// mma.sync / ldmatrix / cp.async helpers (baseline PTX, works on compute_103)
// ---------------------------------------------------------------------------
__device__ __forceinline__ uint32_t smem_u32(const void* p) {
    uint32_t a;
    asm("{ .reg .u64 t; cvta.to.shared.u64 t, %1; cvt.u32.u64 %0, t; }"
        : "=r"(a) : "l"(p));
    return a;
}

__device__ __forceinline__ void ldsm4t(uint32_t* r, uint32_t addr) {
    asm volatile("ldmatrix.sync.aligned.m8n8.x4.trans.shared.b16 {%0,%1,%2,%3}, [%4];"
                 : "=r"(r[0]), "=r"(r[1]), "=r"(r[2]), "=r"(r[3]) : "r"(addr));
}

__device__ __forceinline__ void mma16816(float* c, uint32_t a0, uint32_t a1,
                                         uint32_t a2, uint32_t a3,
                                         uint32_t b0, uint32_t b1) {
    asm volatile(
        "mma.sync.aligned.m16n8k16.row.col.f32.bf16.bf16.f32 "
        "{%0,%1,%2,%3}, {%4,%5,%6,%7}, {%8,%9}, {%0,%1,%2,%3};"
        : "+f"(c[0]), "+f"(c[1]), "+f"(c[2]), "+f"(c[3])
        : "r"(a0), "r"(a1), "r"(a2), "r"(a3), "r"(b0), "r"(b1));
}

__device__ __forceinline__ void cpasync16(uint32_t saddr, const void* g) {
    asm volatile("cp.async.cg.shared.global [%0], [%1], 16;"
                 :: "r"(saddr), "l"(g) : "memory");
}
__device__ __forceinline__ void cpasync_commit() {
    asm volatile("cp.async.commit_group;" ::: "memory");
}
__device__ __forceinline__ void cpasync_wait0() {
    asm volatile("cp.async.wait_group 0;" ::: "memory");
}
__device__ __forceinline__ void cpasync_wait1() {
    asm volatile("cp.async.wait_group 1;" ::: "memory");
}

// ---------------------------------------------------------------------------
// Prep: W transposes (k-major bf16) + zero CTX (65536) and ksum (2048).
// ---------------------------------------------------------------------------
#define CTX_ELEMS (NB * NHEADS * HC * HC)   // 65536

__global__ __launch_bounds__(256) void prep_kernel(
    const float* __restrict__ Wq, const float* __restrict__ Wk,
    const float* __restrict__ Wv, const float* __restrict__ Wr)
{
    if (blockIdx.x < 64) {
        int t = blockIdx.x * 256 + threadIdx.x;   // 0..16383
        const float* Ws[4] = {Wq, Wk, Wv, Wr};
#pragma unroll
        for (int w = 0; w < 4; ++w) {
            const float* W = Ws[w];
            __nv_bfloat16* D = g_Wt + w * 65536;
            for (int idx = t; idx < 65536; idx += 16384) {
                int m = idx >> 8, k = idx & 255;
                D[k * 256 + m] = __float2bfloat16(W[idx]);   // W[m*256+k]
            }
        }
    } else {
        int t = (blockIdx.x - 64) * 256 + threadIdx.x;   // 0..68095
        if (t < CTX_ELEMS) g_CTX[t] = 0.0f;
        int j = t - CTX_ELEMS;
        if (j >= 0 && j < NB * CD) g_ksum[j] = 0.0f;
    }
}

// ---------------------------------------------------------------------------
// HMMA GEMM: Y[n, m, l] = sum_k Wt[k,m] * X[n,k,l] + bias[m] (+ resid)
// FP32IN: X is fp32; staged via cp.async into an fp32 smem stage, each thread
// converts ITS OWN staged data to bf16 after wait_group (no extra sync).
// !FP32IN: X is bf16, cp.async direct (recovery GEMM path).
// Block tile 128(m) x 128(l), BK=32, 8 warps, 3-stage pipeline.
// ---------------------------------------------------------------------------
#define SB 136                          // bf16 row stride (272B)
#define A_BYTES (32 * SB * 2)           // 8704
#define B_BYTES (32 * SB * 2)           // 8704
#define BST_BYTES (32 * 128 * 4)        // 16384 (fp32 stage)
#define STG_F (A_BYTES + B_BYTES + BST_BYTES)   // 33792
#define STG_B (A_BYTES + B_BYTES)               // 17408
#define SMEM_F (3 * STG_F)              // 101376
#define SMEM_B (3 * STG_B)              // 52224

template <bool FP32IN>
__global__ __launch_bounds__(256, 2) void hmma_gemm_kernel(
    const void* __restrict__ X0, const void* __restrict__ X1,
    const void* __restrict__ X2,
    const __nv_bfloat16* __restrict__ Wt0, const __nv_bfloat16* __restrict__ Wt1,
    const __nv_bfloat16* __restrict__ Wt2,
    const float* __restrict__ b0p, const float* __restrict__ b1p,
    const float* __restrict__ b2p,
    float* __restrict__ Y0, float* __restrict__ Y1, float* __restrict__ Y2,
    const float* __restrict__ resid)
{
    extern __shared__ __align__(16) char dsm[];
    constexpr int STG = FP32IN ? STG_F : STG_B;

    const int tid  = threadIdx.x;
    const int wid  = tid >> 5;
    const int lane = tid & 31;
    const int l0   = blockIdx.x * 128;
    const int m0   = blockIdx.y * 128;
    const int proj = blockIdx.z >> 3;
    const int nb   = blockIdx.z & 7;

    const void* Xv;
    const __nv_bfloat16* Wt;
    const float* bias;
    float* Y;
    if (proj == 0)      { Xv = X0; Wt = Wt0; bias = b0p; Y = Y0; }
    else if (proj == 1) { Xv = X1; Wt = Wt1; bias = b1p; Y = Y1; }
    else                { Xv = X2; Wt = Wt2; bias = b2p; Y = Y2; }

    const int m0w = (wid & 3) * 32;   // warp m offset in block
    const int n0w = (wid >> 2) * 64;  // warp n offset in block

    const float* Xf = (const float*)Xv + (size_t)nb * CD * LD;
    const __nv_bfloat16* Xb = (const __nv_bfloat16*)Xv + (size_t)nb * CD * LD;
    float* Yn = Y + (size_t)nb * CD * LD;
    const float* Rn = resid ? resid + (size_t)nb * CD * LD : nullptr;

    float acc[2][8][4];
#pragma unroll
    for (int i = 0; i < 2; i++)
#pragma unroll
        for (int j = 0; j < 8; j++)
#pragma unroll
            for (int e = 0; e < 4; e++) acc[i][j][e] = 0.0f;

    const uint32_t smBase = smem_u32(dsm);
    // A cp.async mapping (both paths)
    const uint32_t chunkA = (uint32_t)((tid >> 4) * (SB * 2) + (tid & 15) * 16);
    const int g_k  = tid >> 4;    // 0..15
    const int g_c8 = (tid & 15) * 8;
    // B bf16-direct mapping (!FP32IN)
    // (reuses chunkA layout: B region row k, col lq*8 bf16)
    // B fp32-stage mapping (FP32IN): thread owns row fk, chunks fch + j*8
    const int fk  = tid >> 3;     // 0..31
    const int fch = tid & 7;      // 0..7
    // ldsm lane offsets
    const uint32_t aOff = (uint32_t)((lane & 15) * (SB * 2) +
                                     (m0w + ((lane >> 4) << 3)) * 2);
    const uint32_t bOff = (uint32_t)(A_BYTES + (lane & 15) * (SB * 2) +
                                     (n0w + ((lane >> 4) << 3)) * 2);

#define G_ISSUE(c)                                                             \
    {                                                                          \
        uint32_t sb = smBase + ((c) % 3) * STG;                                \
        const __nv_bfloat16* gA = Wt + ((c) * 32 + g_k) * 256 + m0 + g_c8;     \
        cpasync16(sb + chunkA, gA);                                            \
        cpasync16(sb + chunkA + 16 * SB * 2, gA + 16 * 256);                   \
        if constexpr (FP32IN) {                                                \
            const float* gB = Xf + (size_t)((c) * 32 + fk) * LD + l0 + fch * 4;\
            _Pragma("unroll")                                                  \
            for (int j = 0; j < 4; ++j)                                        \
                cpasync16(sb + A_BYTES + B_BYTES +                             \
                          (uint32_t)(fk * 512 + (fch + j * 8) * 16),           \
                          gB + j * 32);                                        \
        } else {                                                               \
            const __nv_bfloat16* gB =                                          \
                Xb + (size_t)((c) * 32 + g_k) * LD + l0 + g_c8;                \
            cpasync16(sb + A_BYTES + chunkA, gB);                              \
            cpasync16(sb + A_BYTES + chunkA + 16 * SB * 2,                     \
                      gB + (size_t)16 * LD);                                   \
        }                                                                      \
        cpasync_commit();                                                      \
    }

#define G_CONVERT(c)                                                           \
    if constexpr (FP32IN) {                                                    \
        uint32_t sb = smBase + ((c) % 3) * STG;                                \
        char* p = dsm + ((c) % 3) * STG;                                       \
        (void)sb;                                                              \
        _Pragma("unroll")                                                      \
        for (int j = 0; j < 4; ++j) {                                          \
            float4 v = *(const float4*)(p + A_BYTES + B_BYTES +                \
                                        fk * 512 + (fch + j * 8) * 16);        \
            union { __nv_bfloat162 h[2]; unsigned long long u; } u;            \
            u.h[0] = __float22bfloat162_rn(make_float2(v.x, v.y));             \
            u.h[1] = __float22bfloat162_rn(make_float2(v.z, v.w));             \
            *(unsigned long long*)(p + A_BYTES + fk * SB * 2 +                 \
                                   (fch + j * 8) * 8) = u.u;                   \
        }                                                                      \
    }

    G_ISSUE(0);
    G_ISSUE(1);

#pragma unroll
    for (int c = 0; c < 8; ++c) {
        if (c < 7) cpasync_wait1(); else cpasync_wait0();
        G_CONVERT(c);
        __syncthreads();
        if (c < 6) G_ISSUE(c + 2);

        uint32_t aA = smBase + (c % 3) * STG + aOff;
        uint32_t bA = smBase + (c % 3) * STG + bOff;
#pragma unroll
        for (int ks = 0; ks < 2; ++ks) {
            uint32_t a4[2][4];
#pragma unroll
            for (int im = 0; im < 2; ++im)
                ldsm4t(a4[im], aA + (uint32_t)(ks * 16 * SB * 2 + im * 32));
#pragma unroll
            for (int jp = 0; jp < 4; ++jp) {
                uint32_t b4[4];
                ldsm4t(b4, bA + (uint32_t)(ks * 16 * SB * 2 + jp * 32));
#pragma unroll
                for (int im = 0; im < 2; ++im) {
                    // A fragment from transposed ldsm: {r0, r2, r1, r3}
                    mma16816(acc[im][jp * 2 + 0], a4[im][0], a4[im][2],
                             a4[im][1], a4[im][3], b4[0], b4[1]);
                    mma16816(acc[im][jp * 2 + 1], a4[im][0], a4[im][2],
                             a4[im][1], a4[im][3], b4[2], b4[3]);
                }
            }
        }
        __syncthreads();
    }

    // ---- epilogue: regs -> global, + bias (+ residual)
    const int qr = lane >> 2;        // 0..7
    const int qc = (lane & 3) * 2;   // 0,2,4,6
#pragma unroll
    for (int im = 0; im < 2; ++im) {
        int mA = m0 + m0w + im * 16 + qr;
        int mB = mA + 8;
        float bA = bias[mA];
        float bB = bias[mB];
#pragma unroll
        for (int jn = 0; jn < 8; ++jn) {
            int n = l0 + n0w + jn * 8 + qc;
            size_t gA = (size_t)mA * LD + n;
            size_t gB = (size_t)mB * LD + n;
            float o0 = acc[im][jn][0] + bA;
            float o1 = acc[im][jn][1] + bA;
            float o2 = acc[im][jn][2] + bB;
            float o3 = acc[im][jn][3] + bB;
            if (Rn) {
                float2 rA = *(const float2*)(Rn + gA);
                float2 rB = *(const float2*)(Rn + gB);
                o0 += rA.x; o1 += rA.y; o2 += rB.x; o3 += rB.y;
            }
            float2 vA = {o0, o1};
            float2 vB = {o2, o3};
            *(float2*)(Yn + gA) = vA;
            *(float2*)(Yn + gB) = vB;
        }
    }
}

// ---------------------------------------------------------------------------
// context[n,h,kc,vc] = sum_l exp(K[n,h,kc,l]) * V[n,h,vc,l]   (unnormalized)
// (R14-verified: register tile 4x4, register-prefetch pipeline,
//  row-per-thread float4 STS staging — conflict-free.)
// ---------------------------------------------------------------------------
#define CPAD 36   // floats per l-row (16B aligned, conflict-free fp4 reads)

__global__ __launch_bounds__(256) void context_kernel()
{
    __shared__ float skT[128][CPAD];
    __shared__ float svT[128][CPAD];
    const int n = blockIdx.z, h = blockIdx.y;
    const size_t base = (((size_t)n * NHEADS + h) * HC) * LD;
    const int rowbase = n * CD + h * HC;
    const int tid = threadIdx.x;
    const int grp = tid >> 6;        // 0..3 (l sub-range within 128-tile)
    const int t64 = tid & 63;
    const int kc0 = (t64 >> 3) * 4;  // 0,4,..,28
    const int vc0 = (t64 & 7) * 4;   // 0,4,..,28
    const bool do_ksum = ((t64 & 7) == 0);

    const int sl  = tid & 127;
    const int sc0 = (tid >> 7) * 16;

    float acc[4][4];
#pragma unroll
    for (int i = 0; i < 4; ++i)
#pragma unroll
        for (int j = 0; j < 4; ++j) acc[i][j] = 0.0f;
    float ks[4] = {0.f, 0.f, 0.f, 0.f};

    float rk[16], rv[16];

#define CTX_LOAD(t)                                                            \
    {                                                                          \
        const int l0c = blockIdx.x * 640 + (t) * 128;                          \
        _Pragma("unroll")                                                      \
        for (int j = 0; j < 16; ++j) {                                         \
            rk[j] = g_K[base + (size_t)(sc0 + j) * LD + l0c + sl];             \
            rv[j] = g_V[base + (size_t)(sc0 + j) * LD + l0c + sl];             \
        }                                                                      \
    }

#define CTX_STORE()                                                            \
    {                                                                          \
        _Pragma("unroll")                                                      \
        for (int j4 = 0; j4 < 4; ++j4) {                                       \
            float4 a;                                                          \
            a.x = __expf(rk[j4 * 4 + 0]);                                      \
            a.y = __expf(rk[j4 * 4 + 1]);                                      \
            a.z = __expf(rk[j4 * 4 + 2]);                                      \
            a.w = __expf(rk[j4 * 4 + 3]);                                      \
            *(float4*)&skT[sl][sc0 + j4 * 4] = a;                              \
            float4 b;                                                          \
            b.x = rv[j4 * 4 + 0];                                              \
            b.y = rv[j4 * 4 + 1];                                              \
            b.z = rv[j4 * 4 + 2];                                              \
            b.w = rv[j4 * 4 + 3];                                              \
            *(float4*)&svT[sl][sc0 + j4 * 4] = b;                              \
        }                                                                      \
    }

    CTX_LOAD(0);

    for (int t = 0; t < 5; ++t) {
        CTX_STORE();
        __syncthreads();
        if (t < 4) CTX_LOAD(t + 1);   // LDGs in flight during compute

#pragma unroll 4
        for (int li = 0; li < 32; ++li) {
            int l = grp * 32 + li;
            float4 a4 = *(const float4*)&skT[l][kc0];
            float4 b4 = *(const float4*)&svT[l][vc0];
            float a[4] = {a4.x, a4.y, a4.z, a4.w};
            float b[4] = {b4.x, b4.y, b4.z, b4.w};
#pragma unroll
            for (int i = 0; i < 4; ++i)
#pragma unroll
                for (int j = 0; j < 4; ++j)
                    acc[i][j] += a[i] * b[j];
            if (do_ksum) {
                ks[0] += a[0]; ks[1] += a[1]; ks[2] += a[2]; ks[3] += a[3];
            }
        }
        __syncthreads();
    }

    if (do_ksum) {
#pragma unroll
        for (int i = 0; i < 4; ++i)
            atomicAdd(&g_ksum[rowbase + kc0 + i], ks[i]);
    }
    float* C = g_CTX + (((size_t)n * NHEADS + h) * HC) * HC;
#pragma unroll
    for (int i = 0; i < 4; ++i)
#pragma unroll
        for (int j = 0; j < 4; ++j)
            atomicAdd(&C[(kc0 + i) * HC + vc0 + j], acc[i][j]);
}

// ---------------------------------------------------------------------------
// attended[n,h,vc,l] = sum_kc (ctx[n,h,kc,vc]/ksum[kc]) * softmax_C(q)[n,h,kc,l]
// Writes bf16 directly for the recovery GEMM.
// ---------------------------------------------------------------------------
__global__ __launch_bounds__(128) void attend_kernel()
{
    __shared__ float4 sctx[32][8];
    const int n = blockIdx.z, h = blockIdx.y;
    const int tid = threadIdx.x;
    const int rowbase = n * CD + h * HC;
    {
        const float4* C = (const float4*)(g_CTX + (((size_t)n * NHEADS + h) * HC) * HC);
#pragma unroll
        for (int s = 0; s < 2; s++) {
            int idx = tid + s * 128;
            float inv = 1.0f / g_ksum[rowbase + (idx >> 3)];
            float4 v = C[idx];
            v.x *= inv; v.y *= inv; v.z *= inv; v.w *= inv;
            sctx[idx >> 3][idx & 7] = v;
        }
    }
    __syncthreads();

    const int l = blockIdx.x * 128 + tid;
    const size_t base = (((size_t)n * NHEADS + h) * HC) * LD + l;

    float q[HC];
    float mx = -1e30f;
#pragma unroll
    for (int c = 0; c < HC; c++) {
        q[c] = g_Q[base + (size_t)c * LD];
        mx = fmaxf(mx, q[c]);
    }
    float s = 0.0f;
#pragma unroll
    for (int c = 0; c < HC; c++) {
        q[c] = __expf(q[c] - mx);
        s += q[c];
    }
    float inv = 1.0f / s;
#pragma unroll
    for (int c = 0; c < HC; c++) q[c] *= inv;

    float acc[HC];
#pragma unroll
    for (int v = 0; v < HC; v++) acc[v] = 0.0f;

#pragma unroll
    for (int kc = 0; kc < HC; kc++) {
        float a = q[kc];
#pragma unroll
        for (int vq = 0; vq < 8; vq++) {
            float4 c4 = sctx[kc][vq];
            acc[vq * 4 + 0] += a * c4.x;
            acc[vq * 4 + 1] += a * c4.y;
            acc[vq * 4 + 2] += a * c4.z;
            acc[vq * 4 + 3] += a * c4.w;
        }
    }
#pragma unroll
    for (int v = 0; v < HC; v++)
        g_ATTbf[base + (size_t)v * LD] = __float2bfloat16(acc[v]);
}

// ---------------------------------------------------------------------------
extern "C" void kernel_launch(void* const* d_in, const int* in_sizes, int n_in,
                              void* d_out, int out_size)
{
    const float* qf = (const float*)d_in[0];
    const float* kf = (const float*)d_in[1];
    const float* vf = (const float*)d_in[2];
    const float* Wq = (const float*)d_in[3];
    const float* bq = (const float*)d_in[4];
    const float* Wk = (const float*)d_in[5];
    const float* bk = (const float*)d_in[6];
    const float* Wv = (const float*)d_in[7];
    const float* bv = (const float*)d_in[8];
    const float* Wr = (const float*)d_in[9];
    const float* br = (const float*)d_in[10];
    float* out = (float*)d_out;

    float *Q, *K, *V;
    __nv_bfloat16 *ATTbf, *Wt;
    cudaGetSymbolAddress((void**)&Q,     g_Q);
    cudaGetSymbolAddress((void**)&K,     g_K);
    cudaGetSymbolAddress((void**)&V,     g_V);
    cudaGetSymbolAddress((void**)&ATTbf, g_ATTbf);
    cudaGetSymbolAddress((void**)&Wt,    g_Wt);
    __nv_bfloat16* Wtq = Wt;
    __nv_bfloat16* Wtk = Wt + 65536;
    __nv_bfloat16* Wtv = Wt + 2 * 65536;
    __nv_bfloat16* Wtr = Wt + 3 * 65536;

    cudaFuncSetAttribute(hmma_gemm_kernel<true>,
                         cudaFuncAttributeMaxDynamicSharedMemorySize, SMEM_F);
    cudaFuncSetAttribute(hmma_gemm_kernel<false>,
                         cudaFuncAttributeMaxDynamicSharedMemorySize, SMEM_B);

    prep_kernel<<<330, 256>>>(Wq, Wk, Wv, Wr);                             // 1

    // fused Q/K/V projections reading fp32 inputs directly (in-kernel cvt)
    dim3 fused_grid(LD / 128, CD / 128, 3 * NB);
    hmma_gemm_kernel<true><<<fused_grid, 256, SMEM_F>>>(                   // 2
        kf, qf, vf, Wtk, Wtq, Wtv, bk, bq, bv, K, Q, V, nullptr);

    context_kernel<<<dim3(10, NHEADS, NB), 256>>>();                       // 3
    attend_kernel<<<dim3(LD / 128, NHEADS, NB), 128>>>();                  // 4

    dim3 gemm_grid(LD / 128, CD / 128, NB);
    hmma_gemm_kernel<false><<<gemm_grid, 256, SMEM_B>>>(                   // 5
        ATTbf, ATTbf, ATTbf, Wtr, Wtr, Wtr, br, br, br, out, out, out, qf);
}